// round 16
// baseline (speedup 1.0000x reference)
#include <cuda_runtime.h>
#include <cuda_bf16.h>
#include <math.h>
#include <stdint.h>

// ---------------- problem constants ----------------
#define S_LEN 1024
#define B_SZ  2
#define M_TOK 2048          // B*S
#define H_DIM 2048
#define NHEAD 16
#define NKV   4
#define HD    128
#define QKV_N 3072          // (NH + 2*NKV)*HD
#define E_NUM 16
#define TOPK  4
#define MI    1408
#define SI    5632

// ---------------- scratch (device globals; no allocs allowed) ----------------
__device__ float g_qkv  [(size_t)M_TOK * QKV_N];
__device__ float g_scores[(size_t)B_SZ * NHEAD * S_LEN * S_LEN];
__device__ float g_res  [(size_t)M_TOK * H_DIM];
__device__ float g_h2   [(size_t)M_TOK * H_DIM];
__device__ float g_sout [(size_t)M_TOK * H_DIM];
__device__ float g_logits[(size_t)M_TOK * E_NUM];
__device__ float g_glog [M_TOK];
__device__ float g_sig  [M_TOK];
__device__ float g_combine[(size_t)M_TOK * E_NUM];
__device__ int   g_counts[E_NUM];
__device__ int   g_eidx [(size_t)E_NUM * M_TOK];
__device__ float g_ctab [(size_t)M_TOK * 64];
__device__ float g_stab [(size_t)M_TOK * 64];

// bf16 split operand buffers: [rows, 2K] = [hi(0..K-1), lo(K..2K-1)]
__device__ __nv_bfloat16 g_A2x   [(size_t)M_TOK * 2 * H_DIM];
__device__ __nv_bfloat16 g_A2h2  [(size_t)M_TOK * 2 * H_DIM];
__device__ __nv_bfloat16 g_A2sact[(size_t)M_TOK * 2 * SI];
__device__ __nv_bfloat16 g_A2e   [(size_t)E_NUM * M_TOK * 2 * MI];
__device__ __nv_bfloat16 g_A2q   [(size_t)B_SZ * NHEAD * S_LEN * 2 * HD];
__device__ __nv_bfloat16 g_A2k   [(size_t)B_SZ * NKV * S_LEN * 2 * HD];
__device__ __nv_bfloat16 g_A2vt  [(size_t)B_SZ * NKV * HD * 2 * S_LEN];
__device__ __nv_bfloat16 g_A2p   [(size_t)B_SZ * NHEAD * S_LEN * 2 * S_LEN];
__device__ __nv_bfloat16 g_B2qkv [(size_t)QKV_N * 2 * H_DIM];
__device__ __nv_bfloat16 g_B2o   [(size_t)H_DIM * 2 * H_DIM];
__device__ __nv_bfloat16 g_B2sgu [(size_t)(2*SI) * 2 * H_DIM];
__device__ __nv_bfloat16 g_B2sdn [(size_t)H_DIM * 2 * SI];
__device__ __nv_bfloat16 g_B2w13 [(size_t)E_NUM * (2*MI) * 2 * H_DIM];
__device__ __nv_bfloat16 g_B2w2  [(size_t)E_NUM * H_DIM * 2 * MI];

// ---------------- PTX helpers (compute_103-safe) ----------------
__device__ __forceinline__ uint32_t smem_u32(const void* p) {
    uint32_t a;
    asm("{ .reg .u64 t; cvta.to.shared.u64 t, %1; cvt.u32.u64 %0, t; }" : "=r"(a) : "l"(p));
    return a;
}
__device__ __forceinline__ void cpasync16(uint32_t dst, const void* src) {
    asm volatile("cp.async.cg.shared.global [%0], [%1], 16;" :: "r"(dst), "l"(src));
}
#define CP_COMMIT() asm volatile("cp.async.commit_group;" ::: "memory")
#define CP_WAIT(n)  asm volatile("cp.async.wait_group %0;" :: "n"(n) : "memory")

__device__ __forceinline__ void ldmx4(uint32_t& r0, uint32_t& r1, uint32_t& r2, uint32_t& r3,
                                      uint32_t addr) {
    asm volatile("ldmatrix.sync.aligned.m8n8.x4.shared.b16 {%0,%1,%2,%3}, [%4];"
        : "=r"(r0), "=r"(r1), "=r"(r2), "=r"(r3) : "r"(addr));
}
__device__ __forceinline__ void mma16816(float c[4],
    uint32_t a0, uint32_t a1, uint32_t a2, uint32_t a3,
    uint32_t b0, uint32_t b1)
{
    asm volatile("mma.sync.aligned.m16n8k16.row.col.f32.bf16.bf16.f32 "
        "{%0,%1,%2,%3}, {%4,%5,%6,%7}, {%8,%9}, {%0,%1,%2,%3};"
        : "+f"(c[0]), "+f"(c[1]), "+f"(c[2]), "+f"(c[3])
        : "r"(a0), "r"(a1), "r"(a2), "r"(a3), "r"(b0), "r"(b1));
}
__device__ __forceinline__ void split_store(__nv_bfloat16* hi, __nv_bfloat16* lo, float v) {
    __nv_bfloat16 h = __float2bfloat16(v);
    *hi = h;
    *lo = __float2bfloat16(v - __bfloat162float(h));
}

// ---------------- split-bf16 conversion (16B stores) ----------
// pairHalf>0: within each `period` rows, row rl<pairHalf (gate i) -> 2i,
// row rl>=pairHalf (up i) -> 2i+1. Enables silu-pair GEMM epilogue.
__global__ void k_cvt2(const float* __restrict__ x, __nv_bfloat16* __restrict__ y,
                       long rows, int K, int pairHalf, long period)
{
    int tid = threadIdx.x;
    for (long r = blockIdx.x; r < rows; r += gridDim.x) {
        const float* xr = x + r * (long)K;
        long dstRow = r;
        if (pairHalf > 0) {
            long e = r / period;
            long rl = r - e * period;
            dstRow = e * period + ((rl < pairHalf) ? 2 * rl : 2 * (rl - pairHalf) + 1);
        }
        __nv_bfloat16* yh = y + dstRow * (long)(2 * K);
        __nv_bfloat16* yl = yh + K;
        for (int c = tid * 8; c < K; c += blockDim.x * 8) {
            float4 v0 = *reinterpret_cast<const float4*>(xr + c);
            float4 v1 = *reinterpret_cast<const float4*>(xr + c + 4);
            __nv_bfloat162 hp[4], lp[4];
            float vv[8] = {v0.x, v0.y, v0.z, v0.w, v1.x, v1.y, v1.z, v1.w};
            #pragma unroll
            for (int j = 0; j < 4; j++) {
                __nv_bfloat16 ha = __float2bfloat16(vv[2*j]);
                __nv_bfloat16 hb = __float2bfloat16(vv[2*j+1]);
                hp[j].x = ha; hp[j].y = hb;
                lp[j].x = __float2bfloat16(vv[2*j]   - __bfloat162float(ha));
                lp[j].y = __float2bfloat16(vv[2*j+1] - __bfloat162float(hb));
            }
            *reinterpret_cast<uint4*>(yh + c) = *reinterpret_cast<uint4*>(hp);
            *reinterpret_cast<uint4*>(yl + c) = *reinterpret_cast<uint4*>(lp);
        }
    }
}

// ---------------- bf16 HMMA GEMM (128x128, 8 warps, 64-wide K chunks) ---------
// Virtual K3 = 3K over 2x buffers: seg s -> A offset {0,K,0}[s], B offset {0,0,K}[s]
// mode 0: standard (bias/res/gather/scatter per pointers, blockIdx.z = expert)
// mode 1: attention scores. z=b*NH+h, B z-index = z>>2 (shared KV), causal skip.
// mode 2: attention PV. B z-index = z>>2, Keff = min(K, m0+128),
//         epilogue split-stores into outSplit token rows at head offset.
// mode 3: silu-pair. B rows pair-permuted (gate,up interleaved); epilogue
//         computes silu(a)*b per adjacent column pair, split-stores to outSplit
//         rows of width 2*outK (hi at oc, lo at oc+outK). cStrideZ = outSplit z stride.
#define SROW   72                         // 64 + 8 pad bf16 -> 144B row stride
#define STAGES 3
#define STG_BYTES (128 * SROW * 2)        // 18432 per operand per stage
#define HG_SMEM  (2 * STAGES * STG_BYTES) // 110592

__global__ void __launch_bounds__(256, 2)
k_hgemm(const __nv_bfloat16* __restrict__ A2, long aStrideZ,
        const __nv_bfloat16* __restrict__ B2, long bStrideZ,
        float* __restrict__ C, int ldc, long cStrideZ,
        int M, int K,
        const float* __restrict__ bias,
        const float* __restrict__ res,
        const int* __restrict__ gBase,
        const int* __restrict__ cntArr,
        const float* __restrict__ combine,
        __nv_bfloat16* __restrict__ outSplit, int outK,
        int mode)
{
    const int z = blockIdx.z;
    int mMax = cntArr ? cntArr[z] : M;
    int m0 = blockIdx.y * 128;
    if (m0 >= mMax) return;
    int n0 = blockIdx.x * 128;
    if (mode == 1 && n0 > m0) return;       // fully-masked causal tile

    long bz = (mode == 1 || mode == 2) ? (long)(z >> 2) : (long)z;
    A2 += (long)z * aStrideZ;
    B2 += bz * bStrideZ;
    C  += (long)z * cStrideZ;
    const int* gidx = gBase ? gBase + (long)z * M_TOK : nullptr;

    extern __shared__ char smem[];
    const uint32_t saBase = smem_u32(smem);
    const uint32_t sbBase = saBase + STAGES * STG_BYTES;

    const int tid = threadIdx.x;
    const bool scatter = (combine != nullptr);
    const bool gatherA = (gidx != nullptr) && !scatter;
    const long lda = 2L * K;

    // loader: thread t -> row t>>1, byte half (t&1)*64, 4 x 16B chunks per operand
    const int lrow = tid >> 1;
    const int lcol = (tid & 1) * 32;       // element offset (32 bf16 = 64B)
    int am = m0 + lrow;
    long arow = (am < mMax) ? (gatherA ? (long)gidx[am] : (long)am) : 0;
    const __nv_bfloat16* gA = A2 + arow * lda + lcol;
    const __nv_bfloat16* gB = B2 + (long)(n0 + lrow) * lda + lcol;
    const uint32_t soff = (uint32_t)((lrow * SROW + lcol) * 2);

    const int wid = tid >> 5, lane = tid & 31;
    const int wm = wid & 1, wn = wid >> 1;
    const int g = lane >> 2, t4 = lane & 3;

    const uint32_t aLdRow = (uint32_t)(lane & 15);
    const uint32_t aLdCol = (uint32_t)((lane >> 4) << 3);
    const uint32_t bLdRow = (uint32_t)((lane & 7) + ((lane >> 1) & 8));
    const uint32_t bLdCol = (uint32_t)(lane & 8);

    float acc[4][4][4];
    #pragma unroll
    for (int a = 0; a < 4; a++)
        #pragma unroll
        for (int b = 0; b < 4; b++)
            #pragma unroll
            for (int cc = 0; cc < 4; cc++) acc[a][b][cc] = 0.f;

    const int Keff = (mode == 2) ? min(K, m0 + 128) : K;
    const int ncK = Keff >> 6;             // 64-elem chunks per segment
    const int nChunks = 3 * ncK;

    auto do_load = [&](int chunk, int stage) {
        int seg = (chunk >= 2 * ncK) ? 2 : (chunk >= ncK ? 1 : 0);
        int w = chunk - seg * ncK;
        int aOff = ((seg == 1) ? K : 0) + w * 64;
        int bOff = ((seg == 2) ? K : 0) + w * 64;
        uint32_t sa = saBase + stage * STG_BYTES + soff;
        uint32_t sb = sbBase + stage * STG_BYTES + soff;
        #pragma unroll
        for (int s = 0; s < 4; s++) {
            cpasync16(sa + s * 16, gA + aOff + s * 8);
            cpasync16(sb + s * 16, gB + bOff + s * 8);
        }
    };

    #pragma unroll
    for (int s = 0; s < STAGES - 1; s++) {
        if (s < nChunks) do_load(s, s);
        CP_COMMIT();
    }

    int stage = 0;
    for (int kt = 0; kt < nChunks; kt++) {
        CP_WAIT(STAGES - 2);
        __syncthreads();
        int pre = kt + STAGES - 1;
        if (pre < nChunks) do_load(pre, (stage + STAGES - 1 == 3) ? stage - 1 : stage + STAGES - 1 - ((stage + STAGES - 1 >= STAGES) ? STAGES : 0));
        CP_COMMIT();

        uint32_t sa = saBase + stage * STG_BYTES;
        uint32_t sb = sbBase + stage * STG_BYTES;

        #pragma unroll
        for (int ks = 0; ks < 4; ks++) {
            const uint32_t cb = ks * 16;
            uint32_t af[4][4];
            uint32_t bfr[4][2];
            #pragma unroll
            for (int mt = 0; mt < 4; mt++) {
                uint32_t row = wm * 64 + mt * 16 + aLdRow;
                ldmx4(af[mt][0], af[mt][1], af[mt][2], af[mt][3],
                      sa + (row * SROW + cb + aLdCol) * 2);
            }
            #pragma unroll
            for (int nb = 0; nb < 2; nb++) {
                uint32_t row = wn * 32 + nb * 16 + bLdRow;
                ldmx4(bfr[nb*2][0], bfr[nb*2][1], bfr[nb*2+1][0], bfr[nb*2+1][1],
                      sb + (row * SROW + cb + bLdCol) * 2);
            }
            #pragma unroll
            for (int mt = 0; mt < 4; mt++)
                #pragma unroll
                for (int nt = 0; nt < 4; nt++)
                    mma16816(acc[mt][nt], af[mt][0], af[mt][1], af[mt][2], af[mt][3],
                             bfr[nt][0], bfr[nt][1]);
        }
        stage = (stage + 1 == STAGES) ? 0 : stage + 1;
    }

    // ---- epilogue ----
    const int baseM = m0 + wm * 64;
    const int baseN = n0 + wn * 32;
    #pragma unroll
    for (int mt = 0; mt < 4; mt++) {
        #pragma unroll
        for (int half = 0; half < 2; half++) {
            int rm = baseM + mt * 16 + g + half * 8;
            if (rm >= mMax) continue;

            if (mode == 2) {
                long token = (long)(z >> 4) * S_LEN + rm;
                __nv_bfloat16* orow = outSplit + token * (2 * H_DIM) + (z & 15) * HD;
                #pragma unroll
                for (int nt = 0; nt < 4; nt++) {
                    int cn = baseN + nt * 8 + t4 * 2;
                    float v0 = acc[mt][nt][half * 2 + 0];
                    float v1 = acc[mt][nt][half * 2 + 1];
                    __nv_bfloat162 hp, lp;
                    hp.x = __float2bfloat16(v0);
                    hp.y = __float2bfloat16(v1);
                    lp.x = __float2bfloat16(v0 - __bfloat162float(hp.x));
                    lp.y = __float2bfloat16(v1 - __bfloat162float(hp.y));
                    *reinterpret_cast<__nv_bfloat162*>(orow + cn) = hp;
                    *reinterpret_cast<__nv_bfloat162*>(orow + H_DIM + cn) = lp;
                }
                continue;
            }
            if (mode == 3) {
                __nv_bfloat16* orow = outSplit + (long)z * cStrideZ + (long)rm * (2 * outK);
                #pragma unroll
                for (int nt = 0; nt < 4; nt++) {
                    int cn = baseN + nt * 8 + t4 * 2;
                    float a = acc[mt][nt][half * 2 + 0];
                    float b = acc[mt][nt][half * 2 + 1];
                    float v = a / (1.f + expf(-a)) * b;
                    int oc = cn >> 1;
                    split_store(orow + oc, orow + outK + oc, v);
                }
                continue;
            }

            long crow = rm;
            float wgt = 1.f;
            if (scatter) {
                int tok = gidx[rm];
                crow = tok;
                wgt = combine[(long)tok * E_NUM + z];
            }
            #pragma unroll
            for (int nt = 0; nt < 4; nt++) {
                int cn = baseN + nt * 8 + t4 * 2;
                float v0 = acc[mt][nt][half * 2 + 0];
                float v1 = acc[mt][nt][half * 2 + 1];
                if (bias) { v0 += bias[cn]; v1 += bias[cn + 1]; }
                if (res) {
                    const float2 r2 = *reinterpret_cast<const float2*>(res + crow * ldc + cn);
                    v0 += r2.x; v1 += r2.y;
                }
                if (scatter) {
                    atomicAdd(C + crow * ldc + cn,     wgt * v0);
                    atomicAdd(C + crow * ldc + cn + 1, wgt * v1);
                } else {
                    float2 o2; o2.x = v0; o2.y = v1;
                    *reinterpret_cast<float2*>(C + crow * ldc + cn) = o2;
                }
            }
        }
    }
}

// ---------------- attention operand preparation ----------------
__global__ void k_rope_cvt(const float* __restrict__ qkv,
                           const float* __restrict__ ctab, const float* __restrict__ stab,
                           __nv_bfloat16* __restrict__ A2q, __nv_bfloat16* __restrict__ A2k)
{
    int t = blockIdx.x;
    int h = blockIdx.y;
    int d = threadIdx.x;
    int b = t >> 10;
    int s = t & 1023;
    float c = ctab[t * 64 + d], sn = stab[t * 64 + d];
    const float* v = qkv + (long)t * QKV_N + h * HD;
    float x1 = v[d], x2 = v[d + 64];
    float scale = (h < NHEAD) ? 0.08838834764831845f : 1.f;
    float r1 = (x1 * c - x2 * sn) * scale;
    float r2 = (x2 * c + x1 * sn) * scale;
    __nv_bfloat16* dst;
    if (h < NHEAD) dst = A2q + ((long)(b * NHEAD + h) * S_LEN + s) * (2 * HD);
    else           dst = A2k + ((long)(b * NKV + (h - NHEAD)) * S_LEN + s) * (2 * HD);
    split_store(dst + d,      dst + HD + d,      r1);
    split_store(dst + d + 64, dst + HD + d + 64, r2);
}

__global__ void k_vt_cvt(const float* __restrict__ qkv, __nv_bfloat16* __restrict__ A2vt)
{
    __shared__ float tile[32][33];
    int z = blockIdx.z;
    int b = z >> 2, kvh = z & 3;
    int s0 = blockIdx.x * 32, d0 = blockIdx.y * 32;
    int tx = threadIdx.x, ty = threadIdx.y;
    int vbase = (NHEAD + NKV + kvh) * HD;
    #pragma unroll
    for (int j = 0; j < 32; j += 8)
        tile[ty + j][tx] = qkv[((long)(b * S_LEN + s0 + ty + j)) * QKV_N + vbase + d0 + tx];
    __syncthreads();
    __nv_bfloat16* dst = A2vt + (long)z * HD * 2 * S_LEN;
    #pragma unroll
    for (int j = 0; j < 32; j += 8) {
        int d = d0 + ty + j;
        float val = tile[tx][ty + j];
        split_store(dst + (long)d * 2 * S_LEN + s0 + tx,
                    dst + (long)d * 2 * S_LEN + S_LEN + s0 + tx, val);
    }
}

__global__ void k_softmax_cvt(const float* __restrict__ scores,
                              __nv_bfloat16* __restrict__ A2p)
{
    int q = blockIdx.x;
    long z = blockIdx.y;
    const float* row = scores + z * (long)S_LEN * S_LEN + (long)q * S_LEN;
    __nv_bfloat16* outr = A2p + z * (long)S_LEN * 2 * S_LEN + (long)q * 2 * S_LEN;
    int len = q + 1;
    __shared__ float red[256];
    int tid = threadIdx.x;
    float mx = -1e30f;
    for (int i = tid; i < len; i += 256) mx = fmaxf(mx, row[i]);
    red[tid] = mx; __syncthreads();
    for (int s = 128; s > 0; s >>= 1) { if (tid < s) red[tid] = fmaxf(red[tid], red[tid + s]); __syncthreads(); }
    mx = red[0]; __syncthreads();
    float sum = 0.f;
    for (int i = tid; i < len; i += 256) sum += expf(row[i] - mx);
    red[tid] = sum; __syncthreads();
    for (int s = 128; s > 0; s >>= 1) { if (tid < s) red[tid] += red[tid + s]; __syncthreads(); }
    float inv = 1.f / red[0];
    for (int i = tid; i < S_LEN; i += 256) {
        float pv = (i < len) ? expf(row[i] - mx) * inv : 0.f;
        split_store(outr + i, outr + S_LEN + i, pv);
    }
}

// ---------------- elementwise kernels ----------------
__global__ void k_rmsnorm_cvt(const float* __restrict__ x, const float* __restrict__ w,
                              float* __restrict__ yf, __nv_bfloat16* __restrict__ y2)
{
    int m = blockIdx.x;
    const float* xr = x + (long)m * H_DIM;
    __shared__ float red[256];
    int tid = threadIdx.x;
    float ss = 0.f;
    for (int i = tid; i < H_DIM; i += 256) { float v = xr[i]; ss += v * v; }
    red[tid] = ss; __syncthreads();
    for (int s = 128; s > 0; s >>= 1) { if (tid < s) red[tid] += red[tid + s]; __syncthreads(); }
    float inv = 1.f / sqrtf(red[0] / (float)H_DIM + 1e-6f);
    __nv_bfloat16* yh = y2 + (long)m * 2 * H_DIM;
    float* yfr = yf ? yf + (long)m * H_DIM : nullptr;
    for (int i = tid; i < H_DIM; i += 256) {
        float val = xr[i] * inv * w[i];
        if (yfr) yfr[i] = val;
        split_store(yh + i, yh + H_DIM + i, val);
    }
}

__global__ void k_ropetab(const int* __restrict__ pos, float* __restrict__ ctab,
                          float* __restrict__ stab)
{
    int i = blockIdx.x * blockDim.x + threadIdx.x;
    if (i >= M_TOK * 64) return;
    int t = i >> 6, d = i & 63;
    double f = (double)pos[t] * pow(1.0e6, -(double)d / 64.0);
    ctab[i] = (float)cos(f);
    stab[i] = (float)sin(f);
}

__global__ void k_logits(const float* __restrict__ x, const float* __restrict__ gate_w,
                         const float* __restrict__ sgate_w,
                         float* __restrict__ logits, float* __restrict__ glog)
{
    int m = blockIdx.x;
    const float* xr = x + (long)m * H_DIM;
    __shared__ float red[128];
    int tid = threadIdx.x;
    for (int e = 0; e <= E_NUM; e++) {
        const float* w = (e < E_NUM) ? gate_w + (long)e * H_DIM : sgate_w;
        float p = 0.f;
        for (int i = tid; i < H_DIM; i += 128) p += xr[i] * w[i];
        red[tid] = p; __syncthreads();
        for (int s = 64; s > 0; s >>= 1) { if (tid < s) red[tid] += red[tid + s]; __syncthreads(); }
        if (tid == 0) {
            if (e < E_NUM) logits[(long)m * E_NUM + e] = red[0];
            else glog[m] = red[0];
        }
        __syncthreads();
    }
}

__global__ void k_route(const float* __restrict__ logits, const float* __restrict__ glog,
                        float* __restrict__ combine, float* __restrict__ sig,
                        int* __restrict__ counts, int* __restrict__ eidx)
{
    int m = blockIdx.x * blockDim.x + threadIdx.x;
    if (m >= M_TOK) return;
    float l[E_NUM], p[E_NUM];
    float mx = -1e30f;
    for (int e = 0; e < E_NUM; e++) { l[e] = logits[(long)m * E_NUM + e]; mx = fmaxf(mx, l[e]); }
    float sum = 0.f;
    for (int e = 0; e < E_NUM; e++) { p[e] = expf(l[e] - mx); sum += p[e]; }
    float inv = 1.f / sum;
    for (int e = 0; e < E_NUM; e++) p[e] *= inv;
    for (int e = 0; e < E_NUM; e++) combine[(long)m * E_NUM + e] = 0.f;
    float ps[E_NUM];
    for (int e = 0; e < E_NUM; e++) ps[e] = p[e];
    for (int t = 0; t < TOPK; t++) {
        int arg = 0; float best = ps[0];
        for (int e = 1; e < E_NUM; e++) if (ps[e] > best) { best = ps[e]; arg = e; }
        combine[(long)m * E_NUM + arg] = best;
        ps[arg] = -1.f;
        int posn = atomicAdd(&counts[arg], 1);
        eidx[(long)arg * M_TOK + posn] = m;
    }
    sig[m] = 1.f / (1.f + expf(-glog[m]));
}

// out = sout * sig (w2 scatter then accumulates on top)
__global__ void k_prefill(const float* __restrict__ sout, const float* __restrict__ sig,
                          float* __restrict__ out)
{
    long idx = (long)blockIdx.x * blockDim.x + threadIdx.x;
    if (idx >= (long)M_TOK * H_DIM) return;
    long m = idx / H_DIM;
    out[idx] = sout[idx] * sig[m];
}

// ---------------- launcher ----------------
static inline int rowGrid(long rows) {
    return (int)(rows > 8192 ? 8192 : rows);
}

extern "C" void kernel_launch(void* const* d_in, const int* in_sizes, int n_in,
                              void* d_out, int out_size)
{
    const int*   positions = (const int*)  d_in[0];
    const float* hidden    = (const float*)d_in[1];
    const float* in_ln_w   = (const float*)d_in[2];
    const float* post_ln_w = (const float*)d_in[3];
    const float* qkv_w     = (const float*)d_in[4];
    const float* qkv_b     = (const float*)d_in[5];
    const float* o_w       = (const float*)d_in[6];
    const float* gate_w    = (const float*)d_in[7];
    const float* sgate_w   = (const float*)d_in[8];
    const float* se_gu_w   = (const float*)d_in[9];
    const float* se_down_w = (const float*)d_in[10];
    const float* w13       = (const float*)d_in[11];
    const float* w2        = (const float*)d_in[12];

    float *qkv, *scores, *res, *h2, *sout;
    float *logits, *glog, *sig, *combine, *ctab, *stab;
    int *counts, *eidx;
    __nv_bfloat16 *A2x, *A2h2, *A2sact, *A2e, *A2q, *A2k, *A2vt, *A2p;
    __nv_bfloat16 *B2qkv, *B2o, *B2sgu, *B2sdn, *B2w13, *B2w2;
    cudaGetSymbolAddress((void**)&qkv,     g_qkv);
    cudaGetSymbolAddress((void**)&scores,  g_scores);
    cudaGetSymbolAddress((void**)&res,     g_res);
    cudaGetSymbolAddress((void**)&h2,      g_h2);
    cudaGetSymbolAddress((void**)&sout,    g_sout);
    cudaGetSymbolAddress((void**)&logits,  g_logits);
    cudaGetSymbolAddress((void**)&glog,    g_glog);
    cudaGetSymbolAddress((void**)&sig,     g_sig);
    cudaGetSymbolAddress((void**)&combine, g_combine);
    cudaGetSymbolAddress((void**)&counts,  g_counts);
    cudaGetSymbolAddress((void**)&eidx,    g_eidx);
    cudaGetSymbolAddress((void**)&ctab,    g_ctab);
    cudaGetSymbolAddress((void**)&stab,    g_stab);
    cudaGetSymbolAddress((void**)&A2x,     g_A2x);
    cudaGetSymbolAddress((void**)&A2h2,    g_A2h2);
    cudaGetSymbolAddress((void**)&A2sact,  g_A2sact);
    cudaGetSymbolAddress((void**)&A2e,     g_A2e);
    cudaGetSymbolAddress((void**)&A2q,     g_A2q);
    cudaGetSymbolAddress((void**)&A2k,     g_A2k);
    cudaGetSymbolAddress((void**)&A2vt,    g_A2vt);
    cudaGetSymbolAddress((void**)&A2p,     g_A2p);
    cudaGetSymbolAddress((void**)&B2qkv,   g_B2qkv);
    cudaGetSymbolAddress((void**)&B2o,     g_B2o);
    cudaGetSymbolAddress((void**)&B2sgu,   g_B2sgu);
    cudaGetSymbolAddress((void**)&B2sdn,   g_B2sdn);
    cudaGetSymbolAddress((void**)&B2w13,   g_B2w13);
    cudaGetSymbolAddress((void**)&B2w2,    g_B2w2);

    cudaFuncSetAttribute(k_hgemm, cudaFuncAttributeMaxDynamicSharedMemorySize, HG_SMEM);

    static cudaStream_t s2 = nullptr;
    static cudaEvent_t evFork = nullptr, evJoin = nullptr, evRope = nullptr, evW = nullptr;
    if (!s2) {
        cudaStreamCreateWithFlags(&s2, cudaStreamNonBlocking);
        cudaEventCreateWithFlags(&evFork, cudaEventDisableTiming);
        cudaEventCreateWithFlags(&evJoin, cudaEventDisableTiming);
        cudaEventCreateWithFlags(&evRope, cudaEventDisableTiming);
        cudaEventCreateWithFlags(&evW, cudaEventDisableTiming);
    }

    float* out_moe = (float*)d_out;
    bool both = (out_size >= 2 * M_TOK * H_DIM);
    float* res_dst = both ? (out_moe + (long)M_TOK * H_DIM) : res;

    // ---- fork: all weight conversions + rope table on side stream ----
    cudaEventRecord(evFork, 0);
    cudaStreamWaitEvent(s2, evFork, 0);
    k_ropetab<<<(M_TOK*64 + 255)/256, 256, 0, s2>>>(positions, ctab, stab);
    cudaEventRecord(evRope, s2);
    k_cvt2<<<rowGrid(QKV_N), 256, 0, s2>>>(qkv_w, B2qkv, QKV_N, H_DIM, 0, 0);
    k_cvt2<<<rowGrid(H_DIM), 256, 0, s2>>>(o_w,   B2o,   H_DIM, H_DIM, 0, 0);
    cudaEventRecord(evW, s2);
    k_cvt2<<<rowGrid(2*SI), 256, 0, s2>>>(se_gu_w,   B2sgu, 2*SI,  H_DIM, SI, 2L*SI);
    k_cvt2<<<rowGrid(H_DIM), 256, 0, s2>>>(se_down_w, B2sdn, H_DIM, SI,    0, 0);
    k_cvt2<<<8192, 256, 0, s2>>>(w13, B2w13, (long)E_NUM * 2 * MI, H_DIM, MI, 2L*MI);
    k_cvt2<<<8192, 256, 0, s2>>>(w2,  B2w2,  (long)E_NUM * H_DIM,  MI,    0, 0);
    cudaEventRecord(evJoin, s2);

    // ---- main stream ----
    // 1. input RMSNorm
    k_rmsnorm_cvt<<<M_TOK, 256>>>(hidden, in_ln_w, nullptr, A2x);
    // 2. qkv projection (needs B2qkv)
    cudaStreamWaitEvent(0, evW, 0);
    k_hgemm<<<dim3(QKV_N/128, M_TOK/128, 1), 256, HG_SMEM>>>(
        A2x, 0, B2qkv, 0, qkv, QKV_N, 0, M_TOK, H_DIM,
        qkv_b, nullptr, nullptr, nullptr, nullptr, nullptr, 0, 0);
    // 3. RoPE + split Q/K; V transpose + split
    cudaStreamWaitEvent(0, evRope, 0);
    k_rope_cvt<<<dim3(M_TOK, NHEAD + NKV), 64>>>(qkv, ctab, stab, A2q, A2k);
    k_vt_cvt<<<dim3(S_LEN/32, HD/32, B_SZ*NKV), dim3(32, 8)>>>(qkv, A2vt);
    // 4. scores (causal skip)
    k_hgemm<<<dim3(S_LEN/128, S_LEN/128, B_SZ*NHEAD), 256, HG_SMEM>>>(
        A2q, (long)S_LEN * 2 * HD, A2k, (long)S_LEN * 2 * HD,
        scores, S_LEN, (long)S_LEN * S_LEN, S_LEN, HD,
        nullptr, nullptr, nullptr, nullptr, nullptr, nullptr, 0, 1);
    // 5. softmax + split probs
    k_softmax_cvt<<<dim3(S_LEN, B_SZ*NHEAD), 256>>>(scores, A2p);
    // 6. PV (split-bf16 epilogue straight into o_proj operand A2x)
    k_hgemm<<<dim3(1, S_LEN/128, B_SZ*NHEAD), 256, HG_SMEM>>>(
        A2p, (long)S_LEN * 2 * S_LEN, A2vt, (long)HD * 2 * S_LEN,
        nullptr, 0, 0, S_LEN, S_LEN,
        nullptr, nullptr, nullptr, nullptr, nullptr, A2x, 0, 2);
    // 7. o_proj + residual
    k_hgemm<<<dim3(H_DIM/128, M_TOK/128, 1), 256, HG_SMEM>>>(
        A2x, 0, B2o, 0, res_dst, H_DIM, 0, M_TOK, H_DIM,
        nullptr, hidden, nullptr, nullptr, nullptr, nullptr, 0, 0);
    // 8. post-attn RMSNorm
    k_rmsnorm_cvt<<<M_TOK, 256>>>(res_dst, post_ln_w, h2, A2h2);
    // 12-13. routing
    k_logits<<<M_TOK, 128>>>(h2, gate_w, sgate_w, logits, glog);
    cudaMemsetAsync(counts, 0, E_NUM * sizeof(int));
    k_route<<<(M_TOK + 255)/256, 256>>>(logits, glog, combine, sig, counts, eidx);

    // ---- join: expert weights ready ----
    cudaStreamWaitEvent(0, evJoin, 0);

    // 9-11. shared expert (silu fused into sgu epilogue)
    k_hgemm<<<dim3(2*SI/128, M_TOK/128, 1), 256, HG_SMEM>>>(
        A2h2, 0, B2sgu, 0, nullptr, 0, 0, M_TOK, H_DIM,
        nullptr, nullptr, nullptr, nullptr, nullptr, A2sact, SI, 3);
    k_hgemm<<<dim3(H_DIM/128, M_TOK/128, 1), 256, HG_SMEM>>>(
        A2sact, 0, B2sdn, 0, sout, H_DIM, 0, M_TOK, SI,
        nullptr, nullptr, nullptr, nullptr, nullptr, nullptr, 0, 0);
    // out_moe = sout*sig; w2 accumulates on top
    k_prefill<<<(M_TOK*H_DIM + 255)/256, 256>>>(sout, sig, out_moe);
    // 15. batched MoE (silu fused into w13 epilogue)
    k_hgemm<<<dim3(2*MI/128, M_TOK/128, E_NUM), 256, HG_SMEM>>>(
        A2h2, 0,
        B2w13, (long)(2*MI) * 2 * H_DIM,
        nullptr, 0, (long)M_TOK * 2 * MI,
        M_TOK, H_DIM, nullptr, nullptr, eidx, counts, nullptr, A2e, MI, 3);
    k_hgemm<<<dim3(H_DIM/128, M_TOK/128, E_NUM), 256, HG_SMEM>>>(
        A2e, (long)M_TOK * 2 * MI,
        B2w2, (long)H_DIM * 2 * MI,
        out_moe, H_DIM, 0,
        M_TOK, MI, nullptr, nullptr, eidx, counts, combine, nullptr, 0, 0);
}

// round 17
// speedup vs baseline: 1.3285x; 1.3285x over previous
#include <cuda_runtime.h>
#include <cuda_bf16.h>
#include <math.h>
#include <stdint.h>

// ---------------- problem constants ----------------
#define S_LEN 1024
#define B_SZ  2
#define M_TOK 2048          // B*S
#define H_DIM 2048
#define NHEAD 16
#define NKV   4
#define HD    128
#define QKV_N 3072          // (NH + 2*NKV)*HD
#define E_NUM 16
#define TOPK  4
#define MI    1408
#define SI    5632

// ---------------- scratch (device globals; no allocs allowed) ----------------
__device__ float g_qkv  [(size_t)M_TOK * QKV_N];
__device__ float g_scores[(size_t)B_SZ * NHEAD * S_LEN * S_LEN];
__device__ float g_res  [(size_t)M_TOK * H_DIM];
__device__ float g_h2   [(size_t)M_TOK * H_DIM];
__device__ float g_sout [(size_t)M_TOK * H_DIM];
__device__ float g_logits[(size_t)M_TOK * E_NUM];
__device__ float g_glog [M_TOK];
__device__ float g_sig  [M_TOK];
__device__ float g_combine[(size_t)M_TOK * E_NUM];
__device__ int   g_counts[E_NUM];
__device__ int   g_eidx [(size_t)E_NUM * M_TOK];
__device__ float g_ctab [(size_t)M_TOK * 64];
__device__ float g_stab [(size_t)M_TOK * 64];

// bf16 split operand buffers: [rows, 2K] = [hi(0..K-1), lo(K..2K-1)]
__device__ __nv_bfloat16 g_A2x   [(size_t)M_TOK * 2 * H_DIM];
__device__ __nv_bfloat16 g_A2h2  [(size_t)M_TOK * 2 * H_DIM];
__device__ __nv_bfloat16 g_A2sact[(size_t)M_TOK * 2 * SI];
__device__ __nv_bfloat16 g_A2e   [(size_t)E_NUM * M_TOK * 2 * MI];
__device__ __nv_bfloat16 g_A2q   [(size_t)B_SZ * NHEAD * S_LEN * 2 * HD];
__device__ __nv_bfloat16 g_A2k   [(size_t)B_SZ * NKV * S_LEN * 2 * HD];
__device__ __nv_bfloat16 g_A2vt  [(size_t)B_SZ * NKV * HD * 2 * S_LEN];
__device__ __nv_bfloat16 g_A2p   [(size_t)B_SZ * NHEAD * S_LEN * 2 * S_LEN];
__device__ __nv_bfloat16 g_B2qkv [(size_t)QKV_N * 2 * H_DIM];
__device__ __nv_bfloat16 g_B2o   [(size_t)H_DIM * 2 * H_DIM];
__device__ __nv_bfloat16 g_B2sgu [(size_t)(2*SI) * 2 * H_DIM];
__device__ __nv_bfloat16 g_B2sdn [(size_t)H_DIM * 2 * SI];
__device__ __nv_bfloat16 g_B2w13 [(size_t)E_NUM * (2*MI) * 2 * H_DIM];
__device__ __nv_bfloat16 g_B2w2  [(size_t)E_NUM * H_DIM * 2 * MI];

// ---------------- PTX helpers (compute_103-safe) ----------------
__device__ __forceinline__ uint32_t smem_u32(const void* p) {
    uint32_t a;
    asm("{ .reg .u64 t; cvta.to.shared.u64 t, %1; cvt.u32.u64 %0, t; }" : "=r"(a) : "l"(p));
    return a;
}
__device__ __forceinline__ void cpasync16(uint32_t dst, const void* src) {
    asm volatile("cp.async.cg.shared.global [%0], [%1], 16;" :: "r"(dst), "l"(src));
}
#define CP_COMMIT() asm volatile("cp.async.commit_group;" ::: "memory")
#define CP_WAIT(n)  asm volatile("cp.async.wait_group %0;" :: "n"(n) : "memory")

__device__ __forceinline__ void ldmx4(uint32_t& r0, uint32_t& r1, uint32_t& r2, uint32_t& r3,
                                      uint32_t addr) {
    asm volatile("ldmatrix.sync.aligned.m8n8.x4.shared.b16 {%0,%1,%2,%3}, [%4];"
        : "=r"(r0), "=r"(r1), "=r"(r2), "=r"(r3) : "r"(addr));
}
__device__ __forceinline__ void mma16816(float c[4],
    uint32_t a0, uint32_t a1, uint32_t a2, uint32_t a3,
    uint32_t b0, uint32_t b1)
{
    asm volatile("mma.sync.aligned.m16n8k16.row.col.f32.bf16.bf16.f32 "
        "{%0,%1,%2,%3}, {%4,%5,%6,%7}, {%8,%9}, {%0,%1,%2,%3};"
        : "+f"(c[0]), "+f"(c[1]), "+f"(c[2]), "+f"(c[3])
        : "r"(a0), "r"(a1), "r"(a2), "r"(a3), "r"(b0), "r"(b1));
}
__device__ __forceinline__ void split_store(__nv_bfloat16* hi, __nv_bfloat16* lo, float v) {
    __nv_bfloat16 h = __float2bfloat16(v);
    *hi = h;
    *lo = __float2bfloat16(v - __bfloat162float(h));
}

// ---------------- split-bf16 conversion (16B stores) ----------
// pairHalf>0: within each `period` rows, row rl<pairHalf (gate i) -> 2i,
// row rl>=pairHalf (up i) -> 2i+1. Enables silu-pair GEMM epilogue.
__global__ void k_cvt2(const float* __restrict__ x, __nv_bfloat16* __restrict__ y,
                       long rows, int K, int pairHalf, long period)
{
    int tid = threadIdx.x;
    for (long r = blockIdx.x; r < rows; r += gridDim.x) {
        const float* xr = x + r * (long)K;
        long dstRow = r;
        if (pairHalf > 0) {
            long e = r / period;
            long rl = r - e * period;
            dstRow = e * period + ((rl < pairHalf) ? 2 * rl : 2 * (rl - pairHalf) + 1);
        }
        __nv_bfloat16* yh = y + dstRow * (long)(2 * K);
        __nv_bfloat16* yl = yh + K;
        for (int c = tid * 8; c < K; c += blockDim.x * 8) {
            float4 v0 = *reinterpret_cast<const float4*>(xr + c);
            float4 v1 = *reinterpret_cast<const float4*>(xr + c + 4);
            __nv_bfloat162 hp[4], lp[4];
            float vv[8] = {v0.x, v0.y, v0.z, v0.w, v1.x, v1.y, v1.z, v1.w};
            #pragma unroll
            for (int j = 0; j < 4; j++) {
                __nv_bfloat16 ha = __float2bfloat16(vv[2*j]);
                __nv_bfloat16 hb = __float2bfloat16(vv[2*j+1]);
                hp[j].x = ha; hp[j].y = hb;
                lp[j].x = __float2bfloat16(vv[2*j]   - __bfloat162float(ha));
                lp[j].y = __float2bfloat16(vv[2*j+1] - __bfloat162float(hb));
            }
            *reinterpret_cast<uint4*>(yh + c) = *reinterpret_cast<uint4*>(hp);
            *reinterpret_cast<uint4*>(yl + c) = *reinterpret_cast<uint4*>(lp);
        }
    }
}

// ---------------- bf16 HMMA GEMM (R15 geometry: 128x128, 8 warps, 32-K chunks)
// Virtual K3 = 3K over 2x buffers: seg s -> A offset {0,K,0}[s], B offset {0,0,K}[s]
// mode 0: standard (bias/res/gather/scatter per pointers, blockIdx.z = expert)
// mode 1: attention scores. z=b*NH+h, B z-index = z>>2 (shared KV), causal skip.
// mode 2: attention PV. B z-index = z>>2, Keff = min(K, m0+128),
//         epilogue split-stores into outSplit token rows at head offset.
// mode 3: silu-pair. B rows pair-permuted (gate,up interleaved); epilogue
//         computes silu(a)*b per adjacent column pair, split-stores to outSplit
//         rows of width 2*outK (hi at oc, lo at oc+outK). cStrideZ = outSplit z stride.
#define SROW   40
#define STAGES 4
#define STG_BYTES (128 * SROW * 2)
#define HG_SMEM  (2 * STAGES * STG_BYTES)

__global__ void __launch_bounds__(256, 2)
k_hgemm(const __nv_bfloat16* __restrict__ A2, long aStrideZ,
        const __nv_bfloat16* __restrict__ B2, long bStrideZ,
        float* __restrict__ C, int ldc, long cStrideZ,
        int M, int K,
        const float* __restrict__ bias,
        const float* __restrict__ res,
        const int* __restrict__ gBase,
        const int* __restrict__ cntArr,
        const float* __restrict__ combine,
        __nv_bfloat16* __restrict__ outSplit, int outK,
        int mode)
{
    const int z = blockIdx.z;
    int mMax = cntArr ? cntArr[z] : M;
    int m0 = blockIdx.y * 128;
    if (m0 >= mMax) return;
    int n0 = blockIdx.x * 128;
    if (mode == 1 && n0 > m0) return;       // fully-masked causal tile

    long bz = (mode == 1 || mode == 2) ? (long)(z >> 2) : (long)z;
    A2 += (long)z * aStrideZ;
    B2 += bz * bStrideZ;
    C  += (long)z * cStrideZ;
    const int* gidx = gBase ? gBase + (long)z * M_TOK : nullptr;

    extern __shared__ char smem[];
    const uint32_t saBase = smem_u32(smem);
    const uint32_t sbBase = saBase + STAGES * STG_BYTES;

    const int tid = threadIdx.x;
    const bool scatter = (combine != nullptr);
    const bool gatherA = (gidx != nullptr) && !scatter;
    const long lda = 2L * K;

    const int r0 = tid >> 2;
    const int c8 = (tid & 3) * 8;
    const __nv_bfloat16* gA[2];
    const __nv_bfloat16* gB[2];
    uint32_t soff[2];
    #pragma unroll
    for (int i = 0; i < 2; i++) {
        int row = r0 + i * 64;
        int am = m0 + row;
        long arow = (am < mMax) ? (gatherA ? (long)gidx[am] : (long)am) : 0;
        gA[i] = A2 + arow * lda + c8;
        gB[i] = B2 + (long)(n0 + row) * lda + c8;
        soff[i] = (uint32_t)((row * SROW + c8) * 2);
    }

    const int wid = tid >> 5, lane = tid & 31;
    const int wm = wid & 1, wn = wid >> 1;
    const int g = lane >> 2, t4 = lane & 3;

    const uint32_t aLdRow = (uint32_t)(lane & 15);
    const uint32_t aLdCol = (uint32_t)((lane >> 4) << 3);
    const uint32_t bLdRow = (uint32_t)((lane & 7) + ((lane >> 1) & 8));
    const uint32_t bLdCol = (uint32_t)(lane & 8);

    float acc[4][4][4];
    #pragma unroll
    for (int a = 0; a < 4; a++)
        #pragma unroll
        for (int b = 0; b < 4; b++)
            #pragma unroll
            for (int cc = 0; cc < 4; cc++) acc[a][b][cc] = 0.f;

    const int Keff = (mode == 2) ? min(K, m0 + 128) : K;
    const int ncK = Keff >> 5;
    const int nChunks = 3 * ncK;

    auto do_load = [&](int chunk, int stage) {
        int seg = (chunk >= 2 * ncK) ? 2 : (chunk >= ncK ? 1 : 0);
        int w = chunk - seg * ncK;
        int aOff = ((seg == 1) ? K : 0) + w * 32;
        int bOff = ((seg == 2) ? K : 0) + w * 32;
        uint32_t sa = saBase + stage * STG_BYTES;
        uint32_t sb = sbBase + stage * STG_BYTES;
        #pragma unroll
        for (int i = 0; i < 2; i++) {
            cpasync16(sa + soff[i], gA[i] + aOff);
            cpasync16(sb + soff[i], gB[i] + bOff);
        }
    };

    #pragma unroll
    for (int s = 0; s < STAGES - 1; s++) {
        if (s < nChunks) do_load(s, s);
        CP_COMMIT();
    }

    for (int kt = 0; kt < nChunks; kt++) {
        CP_WAIT(STAGES - 2);
        __syncthreads();
        int pre = kt + STAGES - 1;
        if (pre < nChunks) do_load(pre, pre & (STAGES - 1));
        CP_COMMIT();

        int stage = kt & (STAGES - 1);
        uint32_t sa = saBase + stage * STG_BYTES;
        uint32_t sb = sbBase + stage * STG_BYTES;

        #pragma unroll
        for (int ks = 0; ks < 2; ks++) {
            const uint32_t cb = ks * 16;
            uint32_t af[4][4];
            uint32_t bfr[4][2];
            #pragma unroll
            for (int mt = 0; mt < 4; mt++) {
                uint32_t row = wm * 64 + mt * 16 + aLdRow;
                ldmx4(af[mt][0], af[mt][1], af[mt][2], af[mt][3],
                      sa + (row * SROW + cb + aLdCol) * 2);
            }
            #pragma unroll
            for (int nb = 0; nb < 2; nb++) {
                uint32_t row = wn * 32 + nb * 16 + bLdRow;
                ldmx4(bfr[nb*2][0], bfr[nb*2][1], bfr[nb*2+1][0], bfr[nb*2+1][1],
                      sb + (row * SROW + cb + bLdCol) * 2);
            }
            #pragma unroll
            for (int mt = 0; mt < 4; mt++)
                #pragma unroll
                for (int nt = 0; nt < 4; nt++)
                    mma16816(acc[mt][nt], af[mt][0], af[mt][1], af[mt][2], af[mt][3],
                             bfr[nt][0], bfr[nt][1]);
        }
    }

    // ---- epilogue ----
    const int baseM = m0 + wm * 64;
    const int baseN = n0 + wn * 32;
    #pragma unroll
    for (int mt = 0; mt < 4; mt++) {
        #pragma unroll
        for (int half = 0; half < 2; half++) {
            int rm = baseM + mt * 16 + g + half * 8;
            if (rm >= mMax) continue;

            if (mode == 2) {
                long token = (long)(z >> 4) * S_LEN + rm;
                __nv_bfloat16* orow = outSplit + token * (2 * H_DIM) + (z & 15) * HD;
                #pragma unroll
                for (int nt = 0; nt < 4; nt++) {
                    int cn = baseN + nt * 8 + t4 * 2;
                    float v0 = acc[mt][nt][half * 2 + 0];
                    float v1 = acc[mt][nt][half * 2 + 1];
                    __nv_bfloat162 hp, lp;
                    hp.x = __float2bfloat16(v0);
                    hp.y = __float2bfloat16(v1);
                    lp.x = __float2bfloat16(v0 - __bfloat162float(hp.x));
                    lp.y = __float2bfloat16(v1 - __bfloat162float(hp.y));
                    *reinterpret_cast<__nv_bfloat162*>(orow + cn) = hp;
                    *reinterpret_cast<__nv_bfloat162*>(orow + H_DIM + cn) = lp;
                }
                continue;
            }
            if (mode == 3) {
                __nv_bfloat16* orow = outSplit + (long)z * cStrideZ + (long)rm * (2 * outK);
                #pragma unroll
                for (int nt = 0; nt < 4; nt++) {
                    int cn = baseN + nt * 8 + t4 * 2;
                    float a = acc[mt][nt][half * 2 + 0];
                    float b = acc[mt][nt][half * 2 + 1];
                    float v = a / (1.f + expf(-a)) * b;
                    int oc = cn >> 1;
                    split_store(orow + oc, orow + outK + oc, v);
                }
                continue;
            }

            long crow = rm;
            float wgt = 1.f;
            if (scatter) {
                int tok = gidx[rm];
                crow = tok;
                wgt = combine[(long)tok * E_NUM + z];
            }
            #pragma unroll
            for (int nt = 0; nt < 4; nt++) {
                int cn = baseN + nt * 8 + t4 * 2;
                float v0 = acc[mt][nt][half * 2 + 0];
                float v1 = acc[mt][nt][half * 2 + 1];
                if (bias) { v0 += bias[cn]; v1 += bias[cn + 1]; }
                if (res) {
                    const float2 r2 = *reinterpret_cast<const float2*>(res + crow * ldc + cn);
                    v0 += r2.x; v1 += r2.y;
                }
                if (scatter) {
                    atomicAdd(C + crow * ldc + cn,     wgt * v0);
                    atomicAdd(C + crow * ldc + cn + 1, wgt * v1);
                } else {
                    float2 o2; o2.x = v0; o2.y = v1;
                    *reinterpret_cast<float2*>(C + crow * ldc + cn) = o2;
                }
            }
        }
    }
}

// ---------------- attention operand preparation ----------------
__global__ void k_rope_cvt(const float* __restrict__ qkv,
                           const float* __restrict__ ctab, const float* __restrict__ stab,
                           __nv_bfloat16* __restrict__ A2q, __nv_bfloat16* __restrict__ A2k)
{
    int t = blockIdx.x;
    int h = blockIdx.y;
    int d = threadIdx.x;
    int b = t >> 10;
    int s = t & 1023;
    float c = ctab[t * 64 + d], sn = stab[t * 64 + d];
    const float* v = qkv + (long)t * QKV_N + h * HD;
    float x1 = v[d], x2 = v[d + 64];
    float scale = (h < NHEAD) ? 0.08838834764831845f : 1.f;
    float r1 = (x1 * c - x2 * sn) * scale;
    float r2 = (x2 * c + x1 * sn) * scale;
    __nv_bfloat16* dst;
    if (h < NHEAD) dst = A2q + ((long)(b * NHEAD + h) * S_LEN + s) * (2 * HD);
    else           dst = A2k + ((long)(b * NKV + (h - NHEAD)) * S_LEN + s) * (2 * HD);
    split_store(dst + d,      dst + HD + d,      r1);
    split_store(dst + d + 64, dst + HD + d + 64, r2);
}

__global__ void k_vt_cvt(const float* __restrict__ qkv, __nv_bfloat16* __restrict__ A2vt)
{
    __shared__ float tile[32][33];
    int z = blockIdx.z;
    int b = z >> 2, kvh = z & 3;
    int s0 = blockIdx.x * 32, d0 = blockIdx.y * 32;
    int tx = threadIdx.x, ty = threadIdx.y;
    int vbase = (NHEAD + NKV + kvh) * HD;
    #pragma unroll
    for (int j = 0; j < 32; j += 8)
        tile[ty + j][tx] = qkv[((long)(b * S_LEN + s0 + ty + j)) * QKV_N + vbase + d0 + tx];
    __syncthreads();
    __nv_bfloat16* dst = A2vt + (long)z * HD * 2 * S_LEN;
    #pragma unroll
    for (int j = 0; j < 32; j += 8) {
        int d = d0 + ty + j;
        float val = tile[tx][ty + j];
        split_store(dst + (long)d * 2 * S_LEN + s0 + tx,
                    dst + (long)d * 2 * S_LEN + S_LEN + s0 + tx, val);
    }
}

__global__ void k_softmax_cvt(const float* __restrict__ scores,
                              __nv_bfloat16* __restrict__ A2p)
{
    int q = blockIdx.x;
    long z = blockIdx.y;
    const float* row = scores + z * (long)S_LEN * S_LEN + (long)q * S_LEN;
    __nv_bfloat16* outr = A2p + z * (long)S_LEN * 2 * S_LEN + (long)q * 2 * S_LEN;
    int len = q + 1;
    __shared__ float red[256];
    int tid = threadIdx.x;
    float mx = -1e30f;
    for (int i = tid; i < len; i += 256) mx = fmaxf(mx, row[i]);
    red[tid] = mx; __syncthreads();
    for (int s = 128; s > 0; s >>= 1) { if (tid < s) red[tid] = fmaxf(red[tid], red[tid + s]); __syncthreads(); }
    mx = red[0]; __syncthreads();
    float sum = 0.f;
    for (int i = tid; i < len; i += 256) sum += expf(row[i] - mx);
    red[tid] = sum; __syncthreads();
    for (int s = 128; s > 0; s >>= 1) { if (tid < s) red[tid] += red[tid + s]; __syncthreads(); }
    float inv = 1.f / red[0];
    for (int i = tid; i < S_LEN; i += 256) {
        float pv = (i < len) ? expf(row[i] - mx) * inv : 0.f;
        split_store(outr + i, outr + S_LEN + i, pv);
    }
}

// ---------------- elementwise kernels ----------------
__global__ void k_rmsnorm_cvt(const float* __restrict__ x, const float* __restrict__ w,
                              float* __restrict__ yf, __nv_bfloat16* __restrict__ y2)
{
    int m = blockIdx.x;
    const float* xr = x + (long)m * H_DIM;
    __shared__ float red[256];
    int tid = threadIdx.x;
    float ss = 0.f;
    for (int i = tid; i < H_DIM; i += 256) { float v = xr[i]; ss += v * v; }
    red[tid] = ss; __syncthreads();
    for (int s = 128; s > 0; s >>= 1) { if (tid < s) red[tid] += red[tid + s]; __syncthreads(); }
    float inv = 1.f / sqrtf(red[0] / (float)H_DIM + 1e-6f);
    __nv_bfloat16* yh = y2 + (long)m * 2 * H_DIM;
    float* yfr = yf ? yf + (long)m * H_DIM : nullptr;
    for (int i = tid; i < H_DIM; i += 256) {
        float val = xr[i] * inv * w[i];
        if (yfr) yfr[i] = val;
        split_store(yh + i, yh + H_DIM + i, val);
    }
}

__global__ void k_ropetab(const int* __restrict__ pos, float* __restrict__ ctab,
                          float* __restrict__ stab)
{
    int i = blockIdx.x * blockDim.x + threadIdx.x;
    if (i >= M_TOK * 64) return;
    int t = i >> 6, d = i & 63;
    double f = (double)pos[t] * pow(1.0e6, -(double)d / 64.0);
    ctab[i] = (float)cos(f);
    stab[i] = (float)sin(f);
}

__global__ void k_logits(const float* __restrict__ x, const float* __restrict__ gate_w,
                         const float* __restrict__ sgate_w,
                         float* __restrict__ logits, float* __restrict__ glog)
{
    int m = blockIdx.x;
    const float* xr = x + (long)m * H_DIM;
    __shared__ float red[128];
    int tid = threadIdx.x;
    for (int e = 0; e <= E_NUM; e++) {
        const float* w = (e < E_NUM) ? gate_w + (long)e * H_DIM : sgate_w;
        float p = 0.f;
        for (int i = tid; i < H_DIM; i += 128) p += xr[i] * w[i];
        red[tid] = p; __syncthreads();
        for (int s = 64; s > 0; s >>= 1) { if (tid < s) red[tid] += red[tid + s]; __syncthreads(); }
        if (tid == 0) {
            if (e < E_NUM) logits[(long)m * E_NUM + e] = red[0];
            else glog[m] = red[0];
        }
        __syncthreads();
    }
}

__global__ void k_route(const float* __restrict__ logits, const float* __restrict__ glog,
                        float* __restrict__ combine, float* __restrict__ sig,
                        int* __restrict__ counts, int* __restrict__ eidx)
{
    int m = blockIdx.x * blockDim.x + threadIdx.x;
    if (m >= M_TOK) return;
    float l[E_NUM], p[E_NUM];
    float mx = -1e30f;
    for (int e = 0; e < E_NUM; e++) { l[e] = logits[(long)m * E_NUM + e]; mx = fmaxf(mx, l[e]); }
    float sum = 0.f;
    for (int e = 0; e < E_NUM; e++) { p[e] = expf(l[e] - mx); sum += p[e]; }
    float inv = 1.f / sum;
    for (int e = 0; e < E_NUM; e++) p[e] *= inv;
    for (int e = 0; e < E_NUM; e++) combine[(long)m * E_NUM + e] = 0.f;
    float ps[E_NUM];
    for (int e = 0; e < E_NUM; e++) ps[e] = p[e];
    for (int t = 0; t < TOPK; t++) {
        int arg = 0; float best = ps[0];
        for (int e = 1; e < E_NUM; e++) if (ps[e] > best) { best = ps[e]; arg = e; }
        combine[(long)m * E_NUM + arg] = best;
        ps[arg] = -1.f;
        int posn = atomicAdd(&counts[arg], 1);
        eidx[(long)arg * M_TOK + posn] = m;
    }
    sig[m] = 1.f / (1.f + expf(-glog[m]));
}

// out = sout * sig (w2 scatter then accumulates on top)
__global__ void k_prefill(const float* __restrict__ sout, const float* __restrict__ sig,
                          float* __restrict__ out)
{
    long idx = (long)blockIdx.x * blockDim.x + threadIdx.x;
    if (idx >= (long)M_TOK * H_DIM) return;
    long m = idx / H_DIM;
    out[idx] = sout[idx] * sig[m];
}

// ---------------- launcher ----------------
static inline int rowGrid(long rows) {
    return (int)(rows > 8192 ? 8192 : rows);
}

extern "C" void kernel_launch(void* const* d_in, const int* in_sizes, int n_in,
                              void* d_out, int out_size)
{
    const int*   positions = (const int*)  d_in[0];
    const float* hidden    = (const float*)d_in[1];
    const float* in_ln_w   = (const float*)d_in[2];
    const float* post_ln_w = (const float*)d_in[3];
    const float* qkv_w     = (const float*)d_in[4];
    const float* qkv_b     = (const float*)d_in[5];
    const float* o_w       = (const float*)d_in[6];
    const float* gate_w    = (const float*)d_in[7];
    const float* sgate_w   = (const float*)d_in[8];
    const float* se_gu_w   = (const float*)d_in[9];
    const float* se_down_w = (const float*)d_in[10];
    const float* w13       = (const float*)d_in[11];
    const float* w2        = (const float*)d_in[12];

    float *qkv, *scores, *res, *h2, *sout;
    float *logits, *glog, *sig, *combine, *ctab, *stab;
    int *counts, *eidx;
    __nv_bfloat16 *A2x, *A2h2, *A2sact, *A2e, *A2q, *A2k, *A2vt, *A2p;
    __nv_bfloat16 *B2qkv, *B2o, *B2sgu, *B2sdn, *B2w13, *B2w2;
    cudaGetSymbolAddress((void**)&qkv,     g_qkv);
    cudaGetSymbolAddress((void**)&scores,  g_scores);
    cudaGetSymbolAddress((void**)&res,     g_res);
    cudaGetSymbolAddress((void**)&h2,      g_h2);
    cudaGetSymbolAddress((void**)&sout,    g_sout);
    cudaGetSymbolAddress((void**)&logits,  g_logits);
    cudaGetSymbolAddress((void**)&glog,    g_glog);
    cudaGetSymbolAddress((void**)&sig,     g_sig);
    cudaGetSymbolAddress((void**)&combine, g_combine);
    cudaGetSymbolAddress((void**)&counts,  g_counts);
    cudaGetSymbolAddress((void**)&eidx,    g_eidx);
    cudaGetSymbolAddress((void**)&ctab,    g_ctab);
    cudaGetSymbolAddress((void**)&stab,    g_stab);
    cudaGetSymbolAddress((void**)&A2x,     g_A2x);
    cudaGetSymbolAddress((void**)&A2h2,    g_A2h2);
    cudaGetSymbolAddress((void**)&A2sact,  g_A2sact);
    cudaGetSymbolAddress((void**)&A2e,     g_A2e);
    cudaGetSymbolAddress((void**)&A2q,     g_A2q);
    cudaGetSymbolAddress((void**)&A2k,     g_A2k);
    cudaGetSymbolAddress((void**)&A2vt,    g_A2vt);
    cudaGetSymbolAddress((void**)&A2p,     g_A2p);
    cudaGetSymbolAddress((void**)&B2qkv,   g_B2qkv);
    cudaGetSymbolAddress((void**)&B2o,     g_B2o);
    cudaGetSymbolAddress((void**)&B2sgu,   g_B2sgu);
    cudaGetSymbolAddress((void**)&B2sdn,   g_B2sdn);
    cudaGetSymbolAddress((void**)&B2w13,   g_B2w13);
    cudaGetSymbolAddress((void**)&B2w2,    g_B2w2);

    cudaFuncSetAttribute(k_hgemm, cudaFuncAttributeMaxDynamicSharedMemorySize, HG_SMEM);

    static cudaStream_t s2 = nullptr, s3 = nullptr;
    static cudaEvent_t evFork = nullptr, evJoin = nullptr, evRope = nullptr;
    static cudaEvent_t evQkv = nullptr, evVt = nullptr, evH2 = nullptr, evRoute = nullptr;
    if (!s2) {
        cudaStreamCreateWithFlags(&s2, cudaStreamNonBlocking);
        cudaStreamCreateWithFlags(&s3, cudaStreamNonBlocking);
        cudaEventCreateWithFlags(&evFork, cudaEventDisableTiming);
        cudaEventCreateWithFlags(&evJoin, cudaEventDisableTiming);
        cudaEventCreateWithFlags(&evRope, cudaEventDisableTiming);
        cudaEventCreateWithFlags(&evQkv, cudaEventDisableTiming);
        cudaEventCreateWithFlags(&evVt, cudaEventDisableTiming);
        cudaEventCreateWithFlags(&evH2, cudaEventDisableTiming);
        cudaEventCreateWithFlags(&evRoute, cudaEventDisableTiming);
    }

    float* out_moe = (float*)d_out;
    bool both = (out_size >= 2 * M_TOK * H_DIM);
    float* res_dst = both ? (out_moe + (long)M_TOK * H_DIM) : res;

    // ---- fork: rope table + expert weight conversions on side stream s2 ----
    cudaEventRecord(evFork, 0);
    cudaStreamWaitEvent(s2, evFork, 0);
    k_ropetab<<<(M_TOK*64 + 255)/256, 256, 0, s2>>>(positions, ctab, stab);
    cudaEventRecord(evRope, s2);
    k_cvt2<<<rowGrid(2*SI), 256, 0, s2>>>(se_gu_w,   B2sgu, 2*SI,  H_DIM, SI, 2L*SI);
    k_cvt2<<<rowGrid(H_DIM), 256, 0, s2>>>(se_down_w, B2sdn, H_DIM, SI,    0, 0);
    k_cvt2<<<8192, 256, 0, s2>>>(w13, B2w13, (long)E_NUM * 2 * MI, H_DIM, MI, 2L*MI);
    k_cvt2<<<8192, 256, 0, s2>>>(w2,  B2w2,  (long)E_NUM * H_DIM,  MI,    0, 0);
    cudaEventRecord(evJoin, s2);

    // ---- main stream: attention-path weights ----
    k_cvt2<<<rowGrid(QKV_N), 256>>>(qkv_w, B2qkv, QKV_N, H_DIM, 0, 0);
    k_cvt2<<<rowGrid(H_DIM), 256>>>(o_w,   B2o,   H_DIM, H_DIM, 0, 0);

    // 1. input RMSNorm
    k_rmsnorm_cvt<<<M_TOK, 256>>>(hidden, in_ln_w, nullptr, A2x);
    // 2. qkv projection
    k_hgemm<<<dim3(QKV_N/128, M_TOK/128, 1), 256, HG_SMEM>>>(
        A2x, 0, B2qkv, 0, qkv, QKV_N, 0, M_TOK, H_DIM,
        qkv_b, nullptr, nullptr, nullptr, nullptr, nullptr, 0, 0);
    cudaEventRecord(evQkv, 0);
    // 3a. V transpose + split on s3 (only needed by PV)
    cudaStreamWaitEvent(s3, evQkv, 0);
    k_vt_cvt<<<dim3(S_LEN/32, HD/32, B_SZ*NKV), dim3(32, 8), 0, s3>>>(qkv, A2vt);
    cudaEventRecord(evVt, s3);
    // 3b. RoPE + split Q/K on main
    cudaStreamWaitEvent(0, evRope, 0);
    k_rope_cvt<<<dim3(M_TOK, NHEAD + NKV), 64>>>(qkv, ctab, stab, A2q, A2k);
    // 4. scores (causal skip)
    k_hgemm<<<dim3(S_LEN/128, S_LEN/128, B_SZ*NHEAD), 256, HG_SMEM>>>(
        A2q, (long)S_LEN * 2 * HD, A2k, (long)S_LEN * 2 * HD,
        scores, S_LEN, (long)S_LEN * S_LEN, S_LEN, HD,
        nullptr, nullptr, nullptr, nullptr, nullptr, nullptr, 0, 1);
    // 5. softmax + split probs
    k_softmax_cvt<<<dim3(S_LEN, B_SZ*NHEAD), 256>>>(scores, A2p);
    // 6. PV (split-bf16 epilogue straight into o_proj operand A2x)
    cudaStreamWaitEvent(0, evVt, 0);
    k_hgemm<<<dim3(1, S_LEN/128, B_SZ*NHEAD), 256, HG_SMEM>>>(
        A2p, (long)S_LEN * 2 * S_LEN, A2vt, (long)HD * 2 * S_LEN,
        nullptr, 0, 0, S_LEN, S_LEN,
        nullptr, nullptr, nullptr, nullptr, nullptr, A2x, 0, 2);
    // 7. o_proj + residual
    k_hgemm<<<dim3(H_DIM/128, M_TOK/128, 1), 256, HG_SMEM>>>(
        A2x, 0, B2o, 0, res_dst, H_DIM, 0, M_TOK, H_DIM,
        nullptr, hidden, nullptr, nullptr, nullptr, nullptr, 0, 0);
    // 8. post-attn RMSNorm
    k_rmsnorm_cvt<<<M_TOK, 256>>>(res_dst, post_ln_w, h2, A2h2);
    cudaEventRecord(evH2, 0);
    // 12-13. routing on s3 (overlaps shared-expert GEMMs on main)
    cudaStreamWaitEvent(s3, evH2, 0);
    k_logits<<<M_TOK, 128, 0, s3>>>(h2, gate_w, sgate_w, logits, glog);
    cudaMemsetAsync(counts, 0, E_NUM * sizeof(int), s3);
    k_route<<<(M_TOK + 255)/256, 256, 0, s3>>>(logits, glog, combine, sig, counts, eidx);
    cudaEventRecord(evRoute, s3);

    // ---- join: expert weights ready ----
    cudaStreamWaitEvent(0, evJoin, 0);

    // 9-11. shared expert (silu fused into sgu epilogue)
    k_hgemm<<<dim3(2*SI/128, M_TOK/128, 1), 256, HG_SMEM>>>(
        A2h2, 0, B2sgu, 0, nullptr, 0, 0, M_TOK, H_DIM,
        nullptr, nullptr, nullptr, nullptr, nullptr, A2sact, SI, 3);
    k_hgemm<<<dim3(H_DIM/128, M_TOK/128, 1), 256, HG_SMEM>>>(
        A2sact, 0, B2sdn, 0, sout, H_DIM, 0, M_TOK, SI,
        nullptr, nullptr, nullptr, nullptr, nullptr, nullptr, 0, 0);
    // ---- join: routing ready ----
    cudaStreamWaitEvent(0, evRoute, 0);
    // out_moe = sout*sig; w2 accumulates on top
    k_prefill<<<(M_TOK*H_DIM + 255)/256, 256>>>(sout, sig, out_moe);
    // 15. batched MoE (silu fused into w13 epilogue)
    k_hgemm<<<dim3(2*MI/128, M_TOK/128, E_NUM), 256, HG_SMEM>>>(
        A2h2, 0,
        B2w13, (long)(2*MI) * 2 * H_DIM,
        nullptr, 0, (long)M_TOK * 2 * MI,
        M_TOK, H_DIM, nullptr, nullptr, eidx, counts, nullptr, A2e, MI, 3);
    k_hgemm<<<dim3(H_DIM/128, M_TOK/128, E_NUM), 256, HG_SMEM>>>(
        A2e, (long)M_TOK * 2 * MI,
        B2w2, (long)H_DIM * 2 * MI,
        out_moe, H_DIM, 0,
        M_TOK, MI, nullptr, nullptr, eidx, counts, combine, nullptr, 0, 0);
}